// round 2
// baseline (speedup 1.0000x reference)
#include <cuda_runtime.h>

// Problem constants
#define B_   8
#define QL_  128
#define ML_  1024
#define KS_  512
#define H_   256
#define QG   8        // q rows per block in fused attention kernel

typedef unsigned long long ull;

// ---------- Blackwell packed-f32 helpers ----------
__device__ __forceinline__ ull pack2(float x, float y) {
    ull r; asm("mov.b64 %0, {%1,%2};" : "=l"(r) : "f"(x), "f"(y)); return r;
}
__device__ __forceinline__ void fma2(ull &d, ull a, ull b) {
    asm("fma.rn.f32x2 %0, %1, %2, %0;" : "+l"(d) : "l"(a), "l"(b));
}
__device__ __forceinline__ float2 unpack2(ull v) {
    float2 f; asm("mov.b64 {%0,%1}, %2;" : "=f"(f.x), "=f"(f.y) : "l"(v)); return f;
}
__device__ __forceinline__ float fast_tanh(float x) {
    float r; asm("tanh.approx.f32 %0, %1;" : "=f"(r) : "f"(x)); return r;
}

// ---------- scratch (device globals: no allocations allowed) ----------
__device__ float g_q[B_ * QL_ * H_];          // [B*QL][H]   projected queries
__device__ float g_kT[B_ * H_ * ML_];         // [B][H][ML]  projected keys, transposed
__device__ float g_wscratch[B_ * QL_ * ML_];  // fallback weights sink
__device__ int   g_mask_mode;                 // 0=u8, 1=i32, 2=f32

// ---------- mask dtype auto-detection ----------
// Scans the first B*ML bytes of the mask buffer (valid for every candidate
// dtype) and classifies the byte pattern. Deterministic; runs every launch.
__global__ void detect_mask_kernel(const unsigned char* __restrict__ m) {
    __shared__ int viol[3];
    if (threadIdx.x < 3) viol[threadIdx.x] = 0;
    __syncthreads();
    int v_u8 = 0, v_i32 = 0, v_f32 = 0;
    for (int i = threadIdx.x; i < B_ * ML_; i += 256) {
        unsigned char b = m[i];
        int r = i & 3;
        if (b > 1) v_u8++;                                   // u8 bool: bytes in {0,1}
        if (r != 0 && b != 0) v_i32++;                        // i32 0/1: lead byte only
        if (r == 0 || r == 1) { if (b != 0) v_f32++; }        // f32 0.0/1.0: {0,0,128,63}
        else if (r == 2)      { if (b != 0 && b != 128) v_f32++; }
        else                  { if (b != 0 && b != 63)  v_f32++; }
    }
    atomicAdd(&viol[0], v_u8);
    atomicAdd(&viol[1], v_i32);
    atomicAdd(&viol[2], v_f32);
    __syncthreads();
    if (threadIdx.x == 0) {
        int mode;
        if      (viol[1] == 0) mode = 1;   // int32 pattern holds
        else if (viol[2] == 0) mode = 2;   // float32 pattern holds
        else                   mode = 0;   // uint8
        g_mask_mode = mode;
    }
}

// ---------- GEMM: out = A[M,K] x W[N,K]^T + bias, N = 256 fixed ----------
// kt_mode=0: row-major out[m][n] (q projection)
// kt_mode=1: transposed-per-batch out[b][n][ml]  (k projection -> g_kT)
#define GBM 64
#define GBN 128
#define GBK 16

__global__ __launch_bounds__(256) void gemm_bias_kernel(
    const float* __restrict__ A, const float* __restrict__ W,
    const float* __restrict__ bias, float* __restrict__ out,
    int K, int kt_mode)
{
    __shared__ float As[GBK][GBM];
    __shared__ float Ws[GBK][GBN];

    const int tid = threadIdx.x;
    const int tx = tid & 15;        // -> n (8 cols each)
    const int ty = tid >> 4;        // -> m (4 rows each)
    const int m0 = blockIdx.y * GBM;
    const int n0 = blockIdx.x * GBN;

    ull acc[4][4];
#pragma unroll
    for (int i = 0; i < 4; i++)
#pragma unroll
        for (int j = 0; j < 4; j++) acc[i][j] = 0ull;

    const int arow = tid >> 2;          // 0..63
    const int acol = (tid & 3) << 2;    // 0,4,8,12  (k offset within chunk)

    for (int k0 = 0; k0 < K; k0 += GBK) {
        float4 av = *(const float4*)&A[(size_t)(m0 + arow) * K + k0 + acol];
        As[acol + 0][arow] = av.x; As[acol + 1][arow] = av.y;
        As[acol + 2][arow] = av.z; As[acol + 3][arow] = av.w;

        float4 w0 = *(const float4*)&W[(size_t)(n0 + arow) * K + k0 + acol];
        float4 w1 = *(const float4*)&W[(size_t)(n0 + arow + 64) * K + k0 + acol];
        Ws[acol + 0][arow] = w0.x; Ws[acol + 1][arow] = w0.y;
        Ws[acol + 2][arow] = w0.z; Ws[acol + 3][arow] = w0.w;
        Ws[acol + 0][arow + 64] = w1.x; Ws[acol + 1][arow + 64] = w1.y;
        Ws[acol + 2][arow + 64] = w1.z; Ws[acol + 3][arow + 64] = w1.w;
        __syncthreads();

#pragma unroll
        for (int kk = 0; kk < GBK; kk++) {
            float4 a4  = *(const float4*)&As[kk][ty << 2];
            float4 wv0 = *(const float4*)&Ws[kk][tx << 3];
            float4 wv1 = *(const float4*)&Ws[kk][(tx << 3) + 4];
            ull a2[4] = { pack2(a4.x, a4.x), pack2(a4.y, a4.y),
                          pack2(a4.z, a4.z), pack2(a4.w, a4.w) };
            ull b2[4] = { pack2(wv0.x, wv0.y), pack2(wv0.z, wv0.w),
                          pack2(wv1.x, wv1.y), pack2(wv1.z, wv1.w) };
#pragma unroll
            for (int i = 0; i < 4; i++)
#pragma unroll
                for (int j = 0; j < 4; j++) fma2(acc[i][j], a2[i], b2[j]);
        }
        __syncthreads();
    }

#pragma unroll
    for (int i = 0; i < 4; i++) {
        int m  = m0 + (ty << 2) + i;
        int bb = m >> 10;            // batch (only used in kt_mode)
        int ml = m & 1023;
#pragma unroll
        for (int j = 0; j < 4; j++) {
            float2 v = unpack2(acc[i][j]);
            int na = n0 + (tx << 3) + j * 2;
            float va = v.x + bias[na];
            float vb = v.y + bias[na + 1];
            if (kt_mode) {
                out[((size_t)(bb << 8) + na)     * ML_ + ml] = va;
                out[((size_t)(bb << 8) + na + 1) * ML_ + ml] = vb;
            } else {
                out[(size_t)m * H_ + na]     = va;
                out[(size_t)m * H_ + na + 1] = vb;
            }
        }
    }
}

// ---------- fused logits + softmax + weighted-sum kernel ----------
// grid: (QL/QG, B). block: 512 threads. Each thread owns m = 2t, 2t+1.
__global__ __launch_bounds__(512) void attn_kernel(
    const float* __restrict__ qbuf,     // [B*QL][H]
    const float* __restrict__ kT,       // [B][H][ML]
    const float* __restrict__ memory,   // [B][ML][KS]
    const void* __restrict__ mask_raw,  // [B][ML] dtype per g_mask_mode
    const float* __restrict__ wl, const float* __restrict__ blp,
    float* __restrict__ out_attn, float* __restrict__ out_w)
{
    __shared__ float q_s[QG][H_];                       // 8 KB
    __shared__ float wl_s[H_];                          // 1 KB
    __shared__ __align__(16) float w_s[ML_][QG];        // 32 KB, [m][g]
    __shared__ float red_s[QG * 16];                    // cross-warp scratch

    const int t  = threadIdx.x;
    const int b  = blockIdx.y;
    const int q0 = blockIdx.x * QG;

    for (int i = t; i < QG * H_; i += 512)
        q_s[i >> 8][i & 255] = qbuf[(size_t)(b * QL_ + q0) * H_ + i];
    if (t < H_) wl_s[t] = wl[t];
    __syncthreads();

    const float blv = *blp;
    const float* kb = kT + (size_t)b * H_ * ML_;
    const int m0 = t * 2;

    // ---- phase B: logits (MUFU.TANH-bound) ----
    float lg[2][QG];
#pragma unroll
    for (int g = 0; g < QG; g++) { lg[0][g] = 0.f; lg[1][g] = 0.f; }

#pragma unroll 2
    for (int h = 0; h < H_; h++) {
        float2 kv = *(const float2*)&kb[(size_t)h * ML_ + m0];  // coalesced
        float wlh = wl_s[h];
#pragma unroll
        for (int g = 0; g < QG; g++) {
            float qv = q_s[g][h];
            lg[0][g] = fmaf(wlh, fast_tanh(qv + kv.x), lg[0][g]);
            lg[1][g] = fmaf(wlh, fast_tanh(qv + kv.y), lg[1][g]);
        }
    }

    // mask read honoring detected dtype
    bool mk0, mk1;
    {
        const int mode = g_mask_mode;
        const int idx = b * ML_ + m0;
        if (mode == 1) {
            const int* mi = (const int*)mask_raw;
            mk0 = mi[idx] != 0; mk1 = mi[idx + 1] != 0;
        } else if (mode == 2) {
            const float* mf = (const float*)mask_raw;
            mk0 = mf[idx] != 0.f; mk1 = mf[idx + 1] != 0.f;
        } else {
            const unsigned char* mu = (const unsigned char*)mask_raw;
            mk0 = mu[idx] != 0; mk1 = mu[idx + 1] != 0;
        }
    }
#pragma unroll
    for (int g = 0; g < QG; g++) {
        lg[0][g] = mk0 ? -1e18f : (lg[0][g] + blv);
        lg[1][g] = mk1 ? -1e18f : (lg[1][g] + blv);
    }

    // ---- softmax over m (per g) ----
    const int lane = t & 31, wid = t >> 5;   // 16 warps
    float r[QG];
#pragma unroll
    for (int g = 0; g < QG; g++) r[g] = fmaxf(lg[0][g], lg[1][g]);
#pragma unroll
    for (int o = 16; o > 0; o >>= 1)
#pragma unroll
        for (int g = 0; g < QG; g++)
            r[g] = fmaxf(r[g], __shfl_xor_sync(0xffffffffu, r[g], o));
    if (lane == 0) {
#pragma unroll
        for (int g = 0; g < QG; g++) red_s[g * 16 + wid] = r[g];
    }
    __syncthreads();
    float gmax[QG];
#pragma unroll
    for (int g = 0; g < QG; g++) {
        float mx = red_s[g * 16];
#pragma unroll
        for (int j = 1; j < 16; j++) mx = fmaxf(mx, red_s[g * 16 + j]);
        gmax[g] = mx;
    }
    __syncthreads();   // red_s reuse

    float e0[QG], e1[QG];
#pragma unroll
    for (int g = 0; g < QG; g++) {
        e0[g] = __expf(lg[0][g] - gmax[g]);
        e1[g] = __expf(lg[1][g] - gmax[g]);
        r[g]  = e0[g] + e1[g];
    }
#pragma unroll
    for (int o = 16; o > 0; o >>= 1)
#pragma unroll
        for (int g = 0; g < QG; g++)
            r[g] += __shfl_xor_sync(0xffffffffu, r[g], o);
    if (lane == 0) {
#pragma unroll
        for (int g = 0; g < QG; g++) red_s[g * 16 + wid] = r[g];
    }
    __syncthreads();
    float ginv[QG];
#pragma unroll
    for (int g = 0; g < QG; g++) {
        float s = red_s[g * 16];
#pragma unroll
        for (int j = 1; j < 16; j++) s += red_s[g * 16 + j];
        ginv[g] = 1.0f / s;
    }

    // weights -> smem (for phase C) and gmem output
#pragma unroll
    for (int g = 0; g < QG; g++) {
        float w0v = e0[g] * ginv[g];
        float w1v = e1[g] * ginv[g];
        w_s[m0][g]     = w0v;
        w_s[m0 + 1][g] = w1v;
        *(float2*)&out_w[(size_t)(b * QL_ + q0 + g) * ML_ + m0] = make_float2(w0v, w1v);
    }
    __syncthreads();

    // ---- phase C: attns = weights @ memory (f32x2 FMAs, g paired) ----
    const float* memb = memory + (size_t)b * ML_ * KS_;
    ull acc2[4] = {0ull, 0ull, 0ull, 0ull};
#pragma unroll 4
    for (int m = 0; m < ML_; m++) {
        float mv = memb[(size_t)m * KS_ + t];     // coalesced column read
        ull mv2 = pack2(mv, mv);
#pragma unroll
        for (int gp = 0; gp < 4; gp++) {
            ull wp = *(const ull*)&w_s[m][gp * 2];  // broadcast LDS.64
            fma2(acc2[gp], wp, mv2);
        }
    }
#pragma unroll
    for (int gp = 0; gp < 4; gp++) {
        float2 v = unpack2(acc2[gp]);
        out_attn[(size_t)(b * QL_ + q0 + 2 * gp)     * KS_ + t] = v.x;
        out_attn[(size_t)(b * QL_ + q0 + 2 * gp + 1) * KS_ + t] = v.y;
    }
}

// ---------- launch ----------
extern "C" void kernel_launch(void* const* d_in, const int* in_sizes, int n_in,
                              void* d_out, int out_size) {
    const float* query  = (const float*)d_in[0];
    const float* memory = (const float*)d_in[1];
    const void*  mask   = d_in[2];
    const float* Wq = (const float*)d_in[3];
    const float* bq = (const float*)d_in[4];
    const float* Wk = (const float*)d_in[5];
    const float* bk = (const float*)d_in[6];
    const float* wl = (const float*)d_in[7];
    const float* bl = (const float*)d_in[8];

    float* out = (float*)d_out;
    float *qptr, *kptr, *wscr;
    cudaGetSymbolAddress((void**)&qptr, g_q);
    cudaGetSymbolAddress((void**)&kptr, g_kT);
    cudaGetSymbolAddress((void**)&wscr, g_wscratch);

    // output = concat(attns [B,QL,KS], weights [B,QL,ML])
    float* out_attn = out;
    float* out_w = (out_size >= B_ * QL_ * KS_ + B_ * QL_ * ML_)
                       ? (out + B_ * QL_ * KS_) : wscr;

    // mask dtype probe (writes g_mask_mode)
    detect_mask_kernel<<<1, 256>>>((const unsigned char*)mask);
    // q projection: M = B*QL = 1024
    gemm_bias_kernel<<<dim3(H_ / GBN, (B_ * QL_) / GBM), 256>>>(
        query, Wq, bq, qptr, 512, 0);
    // k projection (transposed store): M = B*ML = 8192
    gemm_bias_kernel<<<dim3(H_ / GBN, (B_ * ML_) / GBM), 256>>>(
        memory, Wk, bk, kptr, 512, 1);
    // fused attention
    attn_kernel<<<dim3(QL_ / QG, B_), 512>>>(
        qptr, kptr, memory, mask, wl, bl, out_attn, out_w);
}

// round 3
// speedup vs baseline: 1.0921x; 1.0921x over previous
#include <cuda_runtime.h>

// Problem constants
#define B_   8
#define QL_  128
#define ML_  1024
#define KS_  512
#define H_   256

typedef unsigned long long ull;

// ---------- Blackwell packed-f32 helpers ----------
__device__ __forceinline__ ull pack2(float x, float y) {
    ull r; asm("mov.b64 %0, {%1,%2};" : "=l"(r) : "f"(x), "f"(y)); return r;
}
__device__ __forceinline__ void fma2(ull &d, ull a, ull b) {
    asm("fma.rn.f32x2 %0, %1, %2, %0;" : "+l"(d) : "l"(a), "l"(b));
}
__device__ __forceinline__ float2 unpack2(ull v) {
    float2 f; asm("mov.b64 {%0,%1}, %2;" : "=f"(f.x), "=f"(f.y) : "l"(v)); return f;
}
__device__ __forceinline__ float fast_tanh(float x) {
    float r; asm("tanh.approx.f32 %0, %1;" : "=f"(r) : "f"(x)); return r;
}

// ---------- scratch (device globals: no allocations allowed) ----------
__device__ float g_q[B_ * QL_ * H_];          // [B*QL][H]
__device__ float g_kT[B_ * H_ * ML_];         // [B][H][ML]
__device__ float g_logits[B_ * QL_ * ML_];    // [B*QL][ML]
__device__ float g_wfallback[B_ * QL_ * ML_]; // weights sink if out has no room
__device__ int   g_mask_mode;                 // 0=u8, 1=i32, 2=f32

// ---------- mask dtype auto-detection ----------
__global__ void detect_mask_kernel(const unsigned char* __restrict__ m) {
    __shared__ int viol[3];
    if (threadIdx.x < 3) viol[threadIdx.x] = 0;
    __syncthreads();
    int v_u8 = 0, v_i32 = 0, v_f32 = 0;
    for (int i = threadIdx.x; i < B_ * ML_; i += 256) {
        unsigned char b = m[i];
        int r = i & 3;
        if (b > 1) v_u8++;
        if (r != 0 && b != 0) v_i32++;
        if (r == 0 || r == 1) { if (b != 0) v_f32++; }
        else if (r == 2)      { if (b != 0 && b != 128) v_f32++; }
        else                  { if (b != 0 && b != 63)  v_f32++; }
    }
    atomicAdd(&viol[0], v_u8);
    atomicAdd(&viol[1], v_i32);
    atomicAdd(&viol[2], v_f32);
    __syncthreads();
    if (threadIdx.x == 0) {
        int mode;
        if      (viol[1] == 0) mode = 1;
        else if (viol[2] == 0) mode = 2;
        else                   mode = 0;
        g_mask_mode = mode;
    }
}

// ---------- projection GEMM: out = A[M,K] x W[N=256,K]^T + bias ----------
#define GBM 64
#define GBN 128
#define GBK 16

__global__ __launch_bounds__(256) void gemm_bias_kernel(
    const float* __restrict__ A, const float* __restrict__ W,
    const float* __restrict__ bias, float* __restrict__ out,
    int K, int kt_mode)
{
    __shared__ float As[GBK][GBM];
    __shared__ float Ws[GBK][GBN];

    const int tid = threadIdx.x;
    const int tx = tid & 15;
    const int ty = tid >> 4;
    const int m0 = blockIdx.y * GBM;
    const int n0 = blockIdx.x * GBN;

    ull acc[4][4];
#pragma unroll
    for (int i = 0; i < 4; i++)
#pragma unroll
        for (int j = 0; j < 4; j++) acc[i][j] = 0ull;

    const int arow = tid >> 2;
    const int acol = (tid & 3) << 2;

    for (int k0 = 0; k0 < K; k0 += GBK) {
        float4 av = *(const float4*)&A[(size_t)(m0 + arow) * K + k0 + acol];
        As[acol + 0][arow] = av.x; As[acol + 1][arow] = av.y;
        As[acol + 2][arow] = av.z; As[acol + 3][arow] = av.w;

        float4 w0 = *(const float4*)&W[(size_t)(n0 + arow) * K + k0 + acol];
        float4 w1 = *(const float4*)&W[(size_t)(n0 + arow + 64) * K + k0 + acol];
        Ws[acol + 0][arow] = w0.x; Ws[acol + 1][arow] = w0.y;
        Ws[acol + 2][arow] = w0.z; Ws[acol + 3][arow] = w0.w;
        Ws[acol + 0][arow + 64] = w1.x; Ws[acol + 1][arow + 64] = w1.y;
        Ws[acol + 2][arow + 64] = w1.z; Ws[acol + 3][arow + 64] = w1.w;
        __syncthreads();

#pragma unroll
        for (int kk = 0; kk < GBK; kk++) {
            float4 a4  = *(const float4*)&As[kk][ty << 2];
            float4 wv0 = *(const float4*)&Ws[kk][tx << 3];
            float4 wv1 = *(const float4*)&Ws[kk][(tx << 3) + 4];
            ull a2[4] = { pack2(a4.x, a4.x), pack2(a4.y, a4.y),
                          pack2(a4.z, a4.z), pack2(a4.w, a4.w) };
            ull b2[4] = { pack2(wv0.x, wv0.y), pack2(wv0.z, wv0.w),
                          pack2(wv1.x, wv1.y), pack2(wv1.z, wv1.w) };
#pragma unroll
            for (int i = 0; i < 4; i++)
#pragma unroll
                for (int j = 0; j < 4; j++) fma2(acc[i][j], a2[i], b2[j]);
        }
        __syncthreads();
    }

#pragma unroll
    for (int i = 0; i < 4; i++) {
        int m  = m0 + (ty << 2) + i;
        int bb = m >> 10;
        int ml = m & 1023;
#pragma unroll
        for (int j = 0; j < 4; j++) {
            float2 v = unpack2(acc[i][j]);
            int na = n0 + (tx << 3) + j * 2;
            float va = v.x + bias[na];
            float vb = v.y + bias[na + 1];
            if (kt_mode) {
                out[((size_t)(bb << 8) + na)     * ML_ + ml] = va;
                out[((size_t)(bb << 8) + na + 1) * ML_ + ml] = vb;
            } else {
                out[(size_t)m * H_ + na]     = va;
                out[(size_t)m * H_ + na + 1] = vb;
            }
        }
    }
}

// ---------- K1: logits (MUFU.TANH-bound) ----------
// grid (QL/4, B), 512 threads; thread owns m = 2t, 2t+1 for 4 q rows.
#define LQG 4
__global__ __launch_bounds__(512) void logits_kernel(
    const float* __restrict__ qbuf,    // [B*QL][H]
    const float* __restrict__ kT,      // [B][H][ML]
    const void* __restrict__ mask_raw, // [B][ML]
    const float* __restrict__ wl, const float* __restrict__ blp,
    float* __restrict__ logits)        // [B*QL][ML]
{
    __shared__ float q_s[LQG][H_];   // 4 KB
    __shared__ float wl_s[H_];       // 1 KB

    const int t  = threadIdx.x;
    const int b  = blockIdx.y;
    const int q0 = blockIdx.x * LQG;

    for (int i = t; i < LQG * H_; i += 512)
        q_s[i >> 8][i & 255] = qbuf[(size_t)(b * QL_ + q0) * H_ + i];
    if (t < H_) wl_s[t] = wl[t];
    __syncthreads();

    const float* kb = kT + (size_t)b * H_ * ML_;
    const int m0 = t * 2;

    float acc[LQG][2];
#pragma unroll
    for (int g = 0; g < LQG; g++) { acc[g][0] = 0.f; acc[g][1] = 0.f; }

#pragma unroll 4
    for (int h = 0; h < H_; h++) {
        float2 kv = *(const float2*)&kb[(size_t)h * ML_ + m0];  // coalesced
        float wlh = wl_s[h];
#pragma unroll
        for (int g = 0; g < LQG; g++) {
            float qv = q_s[g][h];
            acc[g][0] = fmaf(wlh, fast_tanh(qv + kv.x), acc[g][0]);
            acc[g][1] = fmaf(wlh, fast_tanh(qv + kv.y), acc[g][1]);
        }
    }

    bool mk0, mk1;
    {
        const int mode = g_mask_mode;
        const int idx = b * ML_ + m0;
        if (mode == 1) {
            const int* mi = (const int*)mask_raw;
            mk0 = mi[idx] != 0; mk1 = mi[idx + 1] != 0;
        } else if (mode == 2) {
            const float* mf = (const float*)mask_raw;
            mk0 = mf[idx] != 0.f; mk1 = mf[idx + 1] != 0.f;
        } else {
            const unsigned char* mu = (const unsigned char*)mask_raw;
            mk0 = mu[idx] != 0; mk1 = mu[idx + 1] != 0;
        }
    }
    const float blv = *blp;
#pragma unroll
    for (int g = 0; g < LQG; g++) {
        float2 o;
        o.x = mk0 ? -1e18f : (acc[g][0] + blv);
        o.y = mk1 ? -1e18f : (acc[g][1] + blv);
        *(float2*)&logits[(size_t)(b * QL_ + q0 + g) * ML_ + m0] = o;
    }
}

// ---------- K2: softmax over ML per (b,q) row ----------
// grid (B*QL) blocks, 256 threads; thread owns 4 m (float4).
__global__ __launch_bounds__(256) void softmax_kernel(
    const float* __restrict__ logits, float* __restrict__ out_w)
{
    __shared__ float red_s[8];
    const int row = blockIdx.x;
    const int t = threadIdx.x;
    const int lane = t & 31, wid = t >> 5;

    float4 v = *(const float4*)&logits[(size_t)row * ML_ + t * 4];

    float mx = fmaxf(fmaxf(v.x, v.y), fmaxf(v.z, v.w));
#pragma unroll
    for (int o = 16; o > 0; o >>= 1)
        mx = fmaxf(mx, __shfl_xor_sync(0xffffffffu, mx, o));
    if (lane == 0) red_s[wid] = mx;
    __syncthreads();
    float gmax = red_s[0];
#pragma unroll
    for (int j = 1; j < 8; j++) gmax = fmaxf(gmax, red_s[j]);
    __syncthreads();

    float4 e;
    e.x = __expf(v.x - gmax); e.y = __expf(v.y - gmax);
    e.z = __expf(v.z - gmax); e.w = __expf(v.w - gmax);
    float s = (e.x + e.y) + (e.z + e.w);
#pragma unroll
    for (int o = 16; o > 0; o >>= 1)
        s += __shfl_xor_sync(0xffffffffu, s, o);
    if (lane == 0) red_s[wid] = s;
    __syncthreads();
    float gs = red_s[0];
#pragma unroll
    for (int j = 1; j < 8; j++) gs += red_s[j];
    float inv = 1.0f / gs;

    e.x *= inv; e.y *= inv; e.z *= inv; e.w *= inv;
    *(float4*)&out_w[(size_t)row * ML_ + t * 4] = e;
}

// ---------- K3: AV GEMM  attns[b] = weights[b] (128x1024) x memory[b] (1024x512) ----------
#define AM 32
#define AN 64
#define AK 16
__global__ __launch_bounds__(256) void av_gemm_kernel(
    const float* __restrict__ Wt,   // [B][QL][ML]
    const float* __restrict__ Mem,  // [B][ML][KS]
    float* __restrict__ out)        // [B][QL][KS]
{
    __shared__ float As[AK][AM + 1];   // padded: kill 8-way STS conflicts
    __shared__ float Bs[AK][AN];

    const int t  = threadIdx.x;
    const int b  = blockIdx.z;
    const int m0 = blockIdx.y * AM;
    const int n0 = blockIdx.x * AN;

    const float* A  = Wt  + (size_t)b * QL_ * ML_;
    const float* Bm = Mem + (size_t)b * ML_ * KS_;

    const int arow = t >> 3;          // 0..31
    const int ak   = (t & 7) << 1;    // 0,2,..,14
    const int brow = t >> 4;          // 0..15
    const int bn   = (t & 15) << 2;   // 0,4,..,60

    const int tx = t & 15;            // -> 4 n
    const int ty = t >> 4;            // -> 2 m

    ull acc[2][2] = {{0ull, 0ull}, {0ull, 0ull}};

    for (int k0 = 0; k0 < ML_; k0 += AK) {
        float2 av = *(const float2*)&A[(size_t)(m0 + arow) * ML_ + k0 + ak];
        As[ak][arow] = av.x; As[ak + 1][arow] = av.y;
        float4 bv = *(const float4*)&Bm[(size_t)(k0 + brow) * KS_ + n0 + bn];
        *(float4*)&Bs[brow][bn] = bv;
        __syncthreads();

#pragma unroll
        for (int kk = 0; kk < AK; kk++) {
            float a0 = As[kk][ty * 2];
            float a1 = As[kk][ty * 2 + 1];
            ull b0 = *(const ull*)&Bs[kk][tx * 4];
            ull b1 = *(const ull*)&Bs[kk][tx * 4 + 2];
            ull a00 = pack2(a0, a0), a11 = pack2(a1, a1);
            fma2(acc[0][0], a00, b0); fma2(acc[0][1], a00, b1);
            fma2(acc[1][0], a11, b0); fma2(acc[1][1], a11, b1);
        }
        __syncthreads();
    }

#pragma unroll
    for (int i = 0; i < 2; i++) {
        float* orow = &out[(size_t)(b * QL_ + m0 + ty * 2 + i) * KS_ + n0 + tx * 4];
        float2 v0 = unpack2(acc[i][0]);
        float2 v1 = unpack2(acc[i][1]);
        *(float2*)&orow[0] = v0;
        *(float2*)&orow[2] = v1;
    }
}

// ---------- launch ----------
extern "C" void kernel_launch(void* const* d_in, const int* in_sizes, int n_in,
                              void* d_out, int out_size) {
    const float* query  = (const float*)d_in[0];
    const float* memory = (const float*)d_in[1];
    const void*  mask   = d_in[2];
    const float* Wq = (const float*)d_in[3];
    const float* bq = (const float*)d_in[4];
    const float* Wk = (const float*)d_in[5];
    const float* bk = (const float*)d_in[6];
    const float* wl = (const float*)d_in[7];
    const float* bl = (const float*)d_in[8];

    float* out = (float*)d_out;
    float *qptr, *kptr, *lgptr, *wfb;
    cudaGetSymbolAddress((void**)&qptr, g_q);
    cudaGetSymbolAddress((void**)&kptr, g_kT);
    cudaGetSymbolAddress((void**)&lgptr, g_logits);
    cudaGetSymbolAddress((void**)&wfb, g_wfallback);

    // output = concat(attns [B,QL,KS], weights [B,QL,ML])
    float* out_attn = out;
    float* out_w = (out_size >= B_ * QL_ * KS_ + B_ * QL_ * ML_)
                       ? (out + B_ * QL_ * KS_) : wfb;

    detect_mask_kernel<<<1, 256>>>((const unsigned char*)mask);
    gemm_bias_kernel<<<dim3(H_ / GBN, (B_ * QL_) / GBM), 256>>>(
        query, Wq, bq, qptr, 512, 0);
    gemm_bias_kernel<<<dim3(H_ / GBN, (B_ * ML_) / GBM), 256>>>(
        memory, Wk, bk, kptr, 512, 1);
    logits_kernel<<<dim3(QL_ / LQG, B_), 512>>>(
        qptr, kptr, mask, wl, bl, lgptr);
    softmax_kernel<<<B_ * QL_, 256>>>(lgptr, out_w);
    av_gemm_kernel<<<dim3(KS_ / AN, QL_ / AM, B_), 256>>>(
        out_w, memory, out_attn);
}

// round 6
// speedup vs baseline: 1.1524x; 1.0552x over previous
#include <cuda_runtime.h>
#include <cstdint>

// Problem constants
#define B_   8
#define QL_  128
#define ML_  1024
#define KS_  512
#define H_   256

typedef unsigned long long ull;

// ---------- Blackwell packed-f32 helpers ----------
__device__ __forceinline__ ull pack2(float x, float y) {
    ull r; asm("mov.b64 %0, {%1,%2};" : "=l"(r) : "f"(x), "f"(y)); return r;
}
__device__ __forceinline__ void fma2(ull &d, ull a, ull b) {
    asm("fma.rn.f32x2 %0, %1, %2, %0;" : "+l"(d) : "l"(a), "l"(b));
}
__device__ __forceinline__ float2 unpack2(ull v) {
    float2 f; asm("mov.b64 {%0,%1}, %2;" : "=f"(f.x), "=f"(f.y) : "l"(v)); return f;
}
__device__ __forceinline__ float fast_tanh(float x) {
    float r; asm("tanh.approx.f32 %0, %1;" : "=f"(r) : "f"(x)); return r;
}
__device__ __forceinline__ void cp_async16(void* smem_dst, const void* gsrc) {
    unsigned int s = (unsigned int)__cvta_generic_to_shared(smem_dst);
    asm volatile("cp.async.ca.shared.global [%0], [%1], 16;" :: "r"(s), "l"(gsrc) : "memory");
}

// ---------- scratch ----------
__device__ float g_q[B_ * QL_ * H_];          // [B*QL][H]
__device__ float g_kT[B_ * H_ * ML_];         // [B][H][ML]
__device__ float g_wfallback[B_ * QL_ * ML_];
__device__ int   g_mask_mode;                 // 0=u8, 1=i32, 2=f32

// ---------- mask dtype auto-detection ----------
__global__ void detect_mask_kernel(const unsigned char* __restrict__ m) {
    __shared__ int viol[3];
    if (threadIdx.x < 3) viol[threadIdx.x] = 0;
    __syncthreads();
    int v_u8 = 0, v_i32 = 0, v_f32 = 0;
    for (int i = threadIdx.x; i < B_ * ML_; i += 256) {
        unsigned char b = m[i];
        int r = i & 3;
        if (b > 1) v_u8++;
        if (r != 0 && b != 0) v_i32++;
        if (r == 0 || r == 1) { if (b != 0) v_f32++; }
        else if (r == 2)      { if (b != 0 && b != 128) v_f32++; }
        else                  { if (b != 0 && b != 63)  v_f32++; }
    }
    atomicAdd(&viol[0], v_u8);
    atomicAdd(&viol[1], v_i32);
    atomicAdd(&viol[2], v_f32);
    __syncthreads();
    if (threadIdx.x == 0) {
        int mode;
        if      (viol[1] == 0) mode = 1;
        else if (viol[2] == 0) mode = 2;
        else                   mode = 0;
        g_mask_mode = mode;
    }
}

// ---------- projection GEMM: out = A[M,K] x W[N=256,K]^T + bias ----------
#define GBM 64
#define GBN 128
#define GBK 16

__global__ __launch_bounds__(256) void gemm_bias_kernel(
    const float* __restrict__ A, const float* __restrict__ W,
    const float* __restrict__ bias, float* __restrict__ out,
    int K, int kt_mode)
{
    __shared__ float As[GBK][GBM];
    __shared__ float Ws[GBK][GBN];

    const int tid = threadIdx.x;
    const int tx = tid & 15;
    const int ty = tid >> 4;
    const int m0 = blockIdx.y * GBM;
    const int n0 = blockIdx.x * GBN;

    ull acc[4][4];
#pragma unroll
    for (int i = 0; i < 4; i++)
#pragma unroll
        for (int j = 0; j < 4; j++) acc[i][j] = 0ull;

    const int arow = tid >> 2;
    const int acol = (tid & 3) << 2;

    for (int k0 = 0; k0 < K; k0 += GBK) {
        float4 av = *(const float4*)&A[(size_t)(m0 + arow) * K + k0 + acol];
        As[acol + 0][arow] = av.x; As[acol + 1][arow] = av.y;
        As[acol + 2][arow] = av.z; As[acol + 3][arow] = av.w;

        float4 w0 = *(const float4*)&W[(size_t)(n0 + arow) * K + k0 + acol];
        float4 w1 = *(const float4*)&W[(size_t)(n0 + arow + 64) * K + k0 + acol];
        Ws[acol + 0][arow] = w0.x; Ws[acol + 1][arow] = w0.y;
        Ws[acol + 2][arow] = w0.z; Ws[acol + 3][arow] = w0.w;
        Ws[acol + 0][arow + 64] = w1.x; Ws[acol + 1][arow + 64] = w1.y;
        Ws[acol + 2][arow + 64] = w1.z; Ws[acol + 3][arow + 64] = w1.w;
        __syncthreads();

#pragma unroll
        for (int kk = 0; kk < GBK; kk++) {
            float4 a4  = *(const float4*)&As[kk][ty << 2];
            float4 wv0 = *(const float4*)&Ws[kk][tx << 3];
            float4 wv1 = *(const float4*)&Ws[kk][(tx << 3) + 4];
            ull a2[4] = { pack2(a4.x, a4.x), pack2(a4.y, a4.y),
                          pack2(a4.z, a4.z), pack2(a4.w, a4.w) };
            ull b2[4] = { pack2(wv0.x, wv0.y), pack2(wv0.z, wv0.w),
                          pack2(wv1.x, wv1.y), pack2(wv1.z, wv1.w) };
#pragma unroll
            for (int i = 0; i < 4; i++)
#pragma unroll
                for (int j = 0; j < 4; j++) fma2(acc[i][j], a2[i], b2[j]);
        }
        __syncthreads();
    }

#pragma unroll
    for (int i = 0; i < 4; i++) {
        int m  = m0 + (ty << 2) + i;
        int bb = m >> 10;
        int ml = m & 1023;
#pragma unroll
        for (int j = 0; j < 4; j++) {
            float2 v = unpack2(acc[i][j]);
            int na = n0 + (tx << 3) + j * 2;
            float va = v.x + bias[na];
            float vb = v.y + bias[na + 1];
            if (kt_mode) {
                out[((size_t)(bb << 8) + na)     * ML_ + ml] = va;
                out[((size_t)(bb << 8) + na + 1) * ML_ + ml] = vb;
            } else {
                out[(size_t)m * H_ + na]     = va;
                out[(size_t)m * H_ + na + 1] = vb;
            }
        }
    }
}

// ---------- K1: fused logits + softmax -> weights ----------
// grid (QL/4, B), 512 threads; thread owns m = 2t, 2t+1 for 4 q rows.
#define LQG 4
__global__ __launch_bounds__(512) void logits_softmax_kernel(
    const float* __restrict__ qbuf,    // [B*QL][H]
    const float* __restrict__ kT,      // [B][H][ML]
    const void* __restrict__ mask_raw, // [B][ML]
    const float* __restrict__ wl, const float* __restrict__ blp,
    float* __restrict__ out_w)         // [B*QL][ML] softmax weights
{
    __shared__ float q_s[LQG][H_];   // 4 KB
    __shared__ float wl_s[H_];       // 1 KB
    __shared__ float red_s[LQG * 16];

    const int t  = threadIdx.x;
    const int b  = blockIdx.y;
    const int q0 = blockIdx.x * LQG;

    for (int i = t; i < LQG * H_; i += 512)
        q_s[i >> 8][i & 255] = qbuf[(size_t)(b * QL_ + q0) * H_ + i];
    if (t < H_) wl_s[t] = wl[t];
    __syncthreads();

    const float* kb = kT + (size_t)b * H_ * ML_;
    const int m0 = t * 2;

    float lg[LQG][2];
#pragma unroll
    for (int g = 0; g < LQG; g++) { lg[g][0] = 0.f; lg[g][1] = 0.f; }

#pragma unroll 4
    for (int h = 0; h < H_; h++) {
        float2 kv = *(const float2*)&kb[(size_t)h * ML_ + m0];  // coalesced
        float wlh = wl_s[h];
#pragma unroll
        for (int g = 0; g < LQG; g++) {
            float qv = q_s[g][h];
            lg[g][0] = fmaf(wlh, fast_tanh(qv + kv.x), lg[g][0]);
            lg[g][1] = fmaf(wlh, fast_tanh(qv + kv.y), lg[g][1]);
        }
    }

    bool mk0, mk1;
    {
        const int mode = g_mask_mode;
        const int idx = b * ML_ + m0;
        if (mode == 1) {
            const int* mi = (const int*)mask_raw;
            mk0 = mi[idx] != 0; mk1 = mi[idx + 1] != 0;
        } else if (mode == 2) {
            const float* mf = (const float*)mask_raw;
            mk0 = mf[idx] != 0.f; mk1 = mf[idx + 1] != 0.f;
        } else {
            const unsigned char* mu = (const unsigned char*)mask_raw;
            mk0 = mu[idx] != 0; mk1 = mu[idx + 1] != 0;
        }
    }
    const float blv = *blp;
#pragma unroll
    for (int g = 0; g < LQG; g++) {
        lg[g][0] = mk0 ? -1e18f : (lg[g][0] + blv);
        lg[g][1] = mk1 ? -1e18f : (lg[g][1] + blv);
    }

    // ---- softmax over m (block covers the full ML row) ----
    const int lane = t & 31, wid = t >> 5;   // 16 warps
    float r[LQG];
#pragma unroll
    for (int g = 0; g < LQG; g++) r[g] = fmaxf(lg[g][0], lg[g][1]);
#pragma unroll
    for (int o = 16; o > 0; o >>= 1)
#pragma unroll
        for (int g = 0; g < LQG; g++)
            r[g] = fmaxf(r[g], __shfl_xor_sync(0xffffffffu, r[g], o));
    if (lane == 0) {
#pragma unroll
        for (int g = 0; g < LQG; g++) red_s[g * 16 + wid] = r[g];
    }
    __syncthreads();
    float gmax[LQG];
#pragma unroll
    for (int g = 0; g < LQG; g++) {
        float mx = red_s[g * 16];
#pragma unroll
        for (int j = 1; j < 16; j++) mx = fmaxf(mx, red_s[g * 16 + j]);
        gmax[g] = mx;
    }
    __syncthreads();   // red_s reuse

    float e0[LQG], e1[LQG];
#pragma unroll
    for (int g = 0; g < LQG; g++) {
        e0[g] = __expf(lg[g][0] - gmax[g]);
        e1[g] = __expf(lg[g][1] - gmax[g]);
        r[g]  = e0[g] + e1[g];
    }
#pragma unroll
    for (int o = 16; o > 0; o >>= 1)
#pragma unroll
        for (int g = 0; g < LQG; g++)
            r[g] += __shfl_xor_sync(0xffffffffu, r[g], o);
    if (lane == 0) {
#pragma unroll
        for (int g = 0; g < LQG; g++) red_s[g * 16 + wid] = r[g];
    }
    __syncthreads();
#pragma unroll
    for (int g = 0; g < LQG; g++) {
        float s = red_s[g * 16];
#pragma unroll
        for (int j = 1; j < 16; j++) s += red_s[g * 16 + j];
        float inv = 1.0f / s;
        float2 o;
        o.x = e0[g] * inv;
        o.y = e1[g] * inv;
        *(float2*)&out_w[(size_t)(b * QL_ + q0 + g) * ML_ + m0] = o;
    }
}

// ---------- K2: AV GEMM with cp.async double buffering ----------
// attns[b] = weights[b] (128x1024) x memory[b] (1024x512)
#define AM 32
#define AN 64
#define AK 32
#define APAD 36          // As row stride (floats): 16B-aligned, conflict-free reads

__global__ __launch_bounds__(256) void av_gemm_kernel(
    const float* __restrict__ Wt,   // [B][QL][ML]
    const float* __restrict__ Mem,  // [B][ML][KS]
    float* __restrict__ out)        // [B][QL][KS]
{
    __shared__ float As[2][AM * APAD];   // [m][k], padded
    __shared__ float Bs[2][AK * AN];     // [k][n]

    const int t  = threadIdx.x;
    const int b  = blockIdx.z;
    const int m0 = blockIdx.y * AM;
    const int n0 = blockIdx.x * AN;

    const float* A  = Wt  + (size_t)b * QL_ * ML_;
    const float* Bm = Mem + (size_t)b * ML_ * KS_;

    // A stage: 32 rows x 8 chunks(16B) = 256 tasks, 1/thread
    const int a_row = t >> 3, a_ch = t & 7;
    // B stage: 32 rows x 16 chunks = 512 tasks, 2/thread
    const int b_row = t >> 4, b_ch = t & 15;

    const int tx = t & 15;   // -> 4 n
    const int ty = t >> 4;   // -> 2 m

    ull acc[2][2] = {{0ull, 0ull}, {0ull, 0ull}};

#define AV_LOAD(buf, k0)                                                        \
    {                                                                           \
        cp_async16(&As[buf][a_row * APAD + a_ch * 4],                           \
                   &A[(size_t)(m0 + a_row) * ML_ + (k0) + a_ch * 4]);           \
        cp_async16(&Bs[buf][b_row * AN + b_ch * 4],                             \
                   &Bm[(size_t)((k0) + b_row) * KS_ + n0 + b_ch * 4]);          \
        cp_async16(&Bs[buf][(b_row + 16) * AN + b_ch * 4],                      \
                   &Bm[(size_t)((k0) + b_row + 16) * KS_ + n0 + b_ch * 4]);     \
        asm volatile("cp.async.commit_group;" ::: "memory");                    \
    }

    AV_LOAD(0, 0)

    const int NIT = ML_ / AK;   // 32
    for (int it = 0; it < NIT; it++) {
        if (it + 1 < NIT) {
            AV_LOAD((it + 1) & 1, (it + 1) * AK)
            asm volatile("cp.async.wait_group 1;" ::: "memory");
        } else {
            asm volatile("cp.async.wait_group 0;" ::: "memory");
        }
        __syncthreads();

        const float* as = As[it & 1];
        const float* bs = Bs[it & 1];
#pragma unroll
        for (int kk = 0; kk < AK; kk++) {
            float a0 = as[(ty * 2)     * APAD + kk];
            float a1 = as[(ty * 2 + 1) * APAD + kk];
            ull b0 = *(const ull*)&bs[kk * AN + tx * 4];
            ull b1 = *(const ull*)&bs[kk * AN + tx * 4 + 2];
            ull A0 = pack2(a0, a0), A1 = pack2(a1, a1);
            fma2(acc[0][0], A0, b0); fma2(acc[0][1], A0, b1);
            fma2(acc[1][0], A1, b0); fma2(acc[1][1], A1, b1);
        }
        __syncthreads();
    }

#pragma unroll
    for (int i = 0; i < 2; i++) {
        float* orow = &out[(size_t)(b * QL_ + m0 + ty * 2 + i) * KS_ + n0 + tx * 4];
        float2 v0 = unpack2(acc[i][0]);
        float2 v1 = unpack2(acc[i][1]);
        *(float2*)&orow[0] = v0;
        *(float2*)&orow[2] = v1;
    }
#undef AV_LOAD
}

// ---------- launch ----------
extern "C" void kernel_launch(void* const* d_in, const int* in_sizes, int n_in,
                              void* d_out, int out_size) {
    const float* query  = (const float*)d_in[0];
    const float* memory = (const float*)d_in[1];
    const void*  mask   = d_in[2];
    const float* Wq = (const float*)d_in[3];
    const float* bq = (const float*)d_in[4];
    const float* Wk = (const float*)d_in[5];
    const float* bk = (const float*)d_in[6];
    const float* wl = (const float*)d_in[7];
    const float* bl = (const float*)d_in[8];

    float* out = (float*)d_out;
    float *qptr, *kptr, *wfb;
    cudaGetSymbolAddress((void**)&qptr, g_q);
    cudaGetSymbolAddress((void**)&kptr, g_kT);
    cudaGetSymbolAddress((void**)&wfb, g_wfallback);

    // output = concat(attns [B,QL,KS], weights [B,QL,ML])
    float* out_attn = out;
    float* out_w = (out_size >= B_ * QL_ * KS_ + B_ * QL_ * ML_)
                       ? (out + B_ * QL_ * KS_) : wfb;

    detect_mask_kernel<<<1, 256>>>((const unsigned char*)mask);
    gemm_bias_kernel<<<dim3(H_ / GBN, (B_ * QL_) / GBM), 256>>>(
        query, Wq, bq, qptr, 512, 0);
    gemm_bias_kernel<<<dim3(H_ / GBN, (B_ * ML_) / GBM), 256>>>(
        memory, Wk, bk, kptr, 512, 1);
    logits_softmax_kernel<<<dim3(QL_ / LQG, B_), 512>>>(
        qptr, kptr, mask, wl, bl, out_w);
    av_gemm_kernel<<<dim3(KS_ / AN, QL_ / AM, B_), 256>>>(
        out_w, memory, out_attn);
}